// round 10
// baseline (speedup 1.0000x reference)
#include <cuda_runtime.h>
#include <cuda_fp16.h>
#include <cstdint>

#define CTOT 2880
#define NBOX 512

// Raw features in fp16, K-major per level (natural [C][pixel] layout).
__device__ __align__(256) __half g_F0[192 * 9216];
__device__ __align__(256) __half g_F1[384 * 2304];
__device__ __align__(256) __half g_F2[768 * 576];
__device__ __align__(256) __half g_F3[1536 * 192];   // 144 + 48 zero pad
// Projected ROI weight rows per level (sorted box order).
__device__ __align__(256) __half g_A0[NBOX * 9216];
__device__ __align__(256) __half g_A1[NBOX * 2304];
__device__ __align__(256) __half g_A2[NBOX * 576];
__device__ __align__(256) __half g_A3[NBOX * 192];
__device__ int g_perm[NBOX];          // sorted slot -> original box index
__device__ int g_ktlo[8], g_kthi[8];  // per 64-box M-tile: level-0 K-chunk range

// ---------------- boxprep: touched-y range, counting sort by y-center, tile K ranges ----
__global__ __launch_bounds__(256) void k_boxprep(const float* __restrict__ boxes) {
    __shared__ int hist[256], offs[256];
    __shared__ int tlo[8], thi[8];
    __shared__ int wsum[8];
    int t = threadIdx.x;
    hist[t] = 0;
    if (t < 8) { tlo[t] = 1 << 30; thi[t] = -1; }
    __syncthreads();
    int lo[2], hi[2], key[2];
    #pragma unroll
    for (int q = 0; q < 2; q++) {
        int bx = t + q * 256;
        float y1 = boxes[bx * 4 + 1], y2 = boxes[bx * 4 + 3];
        float rh = fmaxf(y2 - y1, 1.f);
        float gh = fminf(fmaxf(ceilf(rh / 7.f), 1.f), 8.f);
        float bb = rh / 7.f;
        int ymin = 95, ymax = 0;
        #pragma unroll
        for (int pp = 0; pp < 7; pp++)
            #pragma unroll
            for (int ss = 0; ss < 8; ss++) {
                if ((float)ss < gh) {
                    float coord = y1 + (float)pp * bb + ((float)ss + 0.5f) * (bb / gh);
                    if (!(coord < -1.f || coord > 96.f)) {
                        float c = fmaxf(coord, 0.f);
                        int i0 = (int)floorf(c);
                        int i1 = (i0 >= 95) ? 95 : i0 + 1;
                        if (i0 > 95) i0 = 95;
                        ymin = min(ymin, i0);
                        ymax = max(ymax, i1);
                    }
                }
            }
        lo[q] = (ymin * 96) / 64;
        hi[q] = (ymax * 96 + 95) / 64;
        key[q] = ymin + ymax;
        atomicAdd(&hist[key[q]], 1);
    }
    __syncthreads();
    // Parallel exclusive prefix scan over 256 bins (warp shuffles + warp-sum scan).
    {
        int h = hist[t];
        int v = h;
        #pragma unroll
        for (int d = 1; d < 32; d <<= 1) {
            int n = __shfl_up_sync(0xFFFFFFFFu, v, d);
            if ((t & 31) >= d) v += n;
        }
        if ((t & 31) == 31) wsum[t >> 5] = v;
        __syncthreads();
        if (t < 8) {
            int w = wsum[t];
            #pragma unroll
            for (int d = 1; d < 8; d <<= 1) {
                int n = __shfl_up_sync(0xFFu, w, d);
                if (t >= d) w += n;
            }
            wsum[t] = w;
        }
        __syncthreads();
        offs[t] = v - h + ((t >= 32) ? wsum[(t >> 5) - 1] : 0);
    }
    __syncthreads();
    #pragma unroll
    for (int q = 0; q < 2; q++) {
        int pos = atomicAdd(&offs[key[q]], 1);
        g_perm[pos] = t + q * 256;
        atomicMin(&tlo[pos >> 6], lo[q]);
        atomicMax(&thi[pos >> 6], hi[q]);
    }
    __syncthreads();
    if (t < 8) { g_ktlo[t] = tlo[t]; g_kthi[t] = thi[t]; }
}

// ---------------- fused weights + converts + pad + out-stripe zero ----------------
// Block ranges: [0,512) per-box weights, [512,728) cvt0, [728,836) cvt1, [836,890) cvt2,
// [890,917) cvt3 data, [917,926) cvt3 pad, [926,998) zero out[:, 0:576).
// Weights blocks are smem/compute-heavy; convert blocks are LDG-heavy -> they overlap.
__device__ __forceinline__ uint4 pack8(float4 a, float4 b) {
    __half2 h[4];
    h[0] = __floats2half2_rn(a.x, a.y);
    h[1] = __floats2half2_rn(a.z, a.w);
    h[2] = __floats2half2_rn(b.x, b.y);
    h[3] = __floats2half2_rn(b.z, b.w);
    return *reinterpret_cast<uint4*>(h);
}

__global__ __launch_bounds__(256) void k_wc(
    const float4* __restrict__ f0, const float4* __restrict__ f1,
    const float4* __restrict__ f2, const float*  __restrict__ f3,
    const float*  __restrict__ boxes, float4* __restrict__ out4)
{
    int b = blockIdx.x, t = threadIdx.x;
    if (b < 512) {
        // ---- per-box weights: build Ax/Ay, project through upsample, write A0..A3 ----
        __shared__ float Ax[96], Ay[96];
        __shared__ float AxP[84], AyP[84];   // [0,48) L1, [48,72) L2, [72,84) L3
        __shared__ float s_norm;
        int slot = b;
        int k = g_perm[slot];
        if (t < 96) { Ax[t] = 0.f; Ay[t] = 0.f; }
        if (t < 84) { AxP[t] = 0.f; AyP[t] = 0.f; }
        float x1 = boxes[k*4+0], y1 = boxes[k*4+1];
        float x2 = boxes[k*4+2], y2 = boxes[k*4+3];
        float rw = fmaxf(x2 - x1, 1.0f), rh = fmaxf(y2 - y1, 1.0f);
        float gw = fminf(fmaxf(ceilf(rw / 7.0f), 1.0f), 8.0f);
        float gh = fminf(fmaxf(ceilf(rh / 7.0f), 1.0f), 8.0f);
        if (t == 0) s_norm = 1.0f / (gh * gw * 49.0f);
        __syncthreads();
        if (t < 112) {
            int isY = t >= 56;
            int i = isY ? t - 56 : t;
            int pp = i >> 3, ss = i & 7;
            float lo = isY ? y1 : x1;
            float sz = isY ? rh : rw;
            float g  = isY ? gh : gw;
            float* Aarr = isY ? Ay : Ax;
            if ((float)ss < g) {
                float bb = sz / 7.0f;
                float coord = lo + (float)pp * bb + ((float)ss + 0.5f) * (bb / g);
                if (!(coord < -1.0f || coord > 96.0f)) {
                    float c = fmaxf(coord, 0.0f);
                    int i0 = (int)floorf(c);
                    int i1; float f;
                    if (i0 >= 95) { i0 = 95; i1 = 95; f = 0.f; }
                    else          { i1 = i0 + 1; f = c - (float)i0; }
                    atomicAdd(&Aarr[i0], 1.0f - f);
                    atomicAdd(&Aarr[i1], f);
                }
            }
        }
        __syncthreads();
        // Project through the bilinear upsample: A_l = U_l^T A (separable, per axis).
        if (t < 96) {
            float axv = Ax[t], ayv = Ay[t];
            auto proj = [&](float* dst, float v, int HS, float sc) {
                float Xf = ((float)t + 0.5f) * sc - 0.5f;
                float Xc = fminf(fmaxf(Xf, 0.f), (float)(HS - 1));
                int x0 = min((int)Xc, HS - 2);
                float f = Xc - (float)x0;
                atomicAdd(dst + x0, v * (1.f - f));
                atomicAdd(dst + x0 + 1, v * f);
            };
            proj(AxP + 0,  axv, 48, 0.5f);   proj(AyP + 0,  ayv, 48, 0.5f);
            proj(AxP + 48, axv, 24, 0.25f);  proj(AyP + 48, ayv, 24, 0.25f);
            proj(AxP + 72, axv, 12, 0.125f); proj(AyP + 72, ayv, 12, 0.125f);
        }
        __syncthreads();
        float norm = s_norm;
        // A0: only this tile's K-chunk union (all the GEMM ever reads).
        {
            int plo = g_ktlo[slot >> 6] * 64;
            int phi = (g_kthi[slot >> 6] + 1) * 64;
            __half* row = g_A0 + (size_t)slot * 9216;
            for (int e = plo + t * 8; e < phi; e += 256 * 8) {
                int y = e / 96, x = e - y * 96;
                float vy = norm * Ay[y];
                __align__(16) __half h[8];
                #pragma unroll
                for (int i = 0; i < 8; i++) h[i] = __float2half(vy * Ax[x + i]);
                *(uint4*)(row + e) = *reinterpret_cast<uint4*>(h);
            }
        }
        // A1: 48x48
        {
            __half* row = g_A1 + (size_t)slot * 2304;
            for (int e = t * 8; e < 2304; e += 256 * 8) {
                int y = e / 48, x = e - y * 48;
                float vy = norm * AyP[y];
                __align__(16) __half h[8];
                #pragma unroll
                for (int i = 0; i < 8; i++) h[i] = __float2half(vy * AxP[x + i]);
                *(uint4*)(row + e) = *reinterpret_cast<uint4*>(h);
            }
        }
        // A2: 24x24
        {
            __half* row = g_A2 + (size_t)slot * 576;
            if (t * 8 < 576) {
                int e = t * 8;
                int y = e / 24, x = e - y * 24;
                float vy = norm * AyP[48 + y];
                __align__(16) __half h[8];
                #pragma unroll
                for (int i = 0; i < 8; i++) h[i] = __float2half(vy * AxP[48 + x + i]);
                *(uint4*)(row + e) = *reinterpret_cast<uint4*>(h);
            }
        }
        // A3: 12x12 + zero pad to 192
        {
            __half* row = g_A3 + (size_t)slot * 192;
            if (t < 192) {
                float v = 0.f;
                if (t < 144) v = norm * AyP[72 + t / 12] * AxP[72 + t % 12];
                row[t] = __float2half(v);
            }
        }
    } else if (b < 728) {
        int i0 = (b - 512) * 1024 + t;
        uint4* dst = reinterpret_cast<uint4*>(g_F0);
        float4 a[4], c[4];
        #pragma unroll
        for (int k = 0; k < 4; k++) { int i = i0 + k * 256; a[k] = f0[2*i]; c[k] = f0[2*i+1]; }
        #pragma unroll
        for (int k = 0; k < 4; k++) dst[i0 + k * 256] = pack8(a[k], c[k]);
    } else if (b < 836) {
        int i0 = (b - 728) * 1024 + t;
        uint4* dst = reinterpret_cast<uint4*>(g_F1);
        float4 a[4], c[4];
        #pragma unroll
        for (int k = 0; k < 4; k++) { int i = i0 + k * 256; a[k] = f1[2*i]; c[k] = f1[2*i+1]; }
        #pragma unroll
        for (int k = 0; k < 4; k++) dst[i0 + k * 256] = pack8(a[k], c[k]);
    } else if (b < 890) {
        int i0 = (b - 836) * 1024 + t;
        uint4* dst = reinterpret_cast<uint4*>(g_F2);
        float4 a[4], c[4];
        #pragma unroll
        for (int k = 0; k < 4; k++) { int i = i0 + k * 256; a[k] = f2[2*i]; c[k] = f2[2*i+1]; }
        #pragma unroll
        for (int k = 0; k < 4; k++) dst[i0 + k * 256] = pack8(a[k], c[k]);
    } else if (b < 917) {
        int i0 = (b - 890) * 1024 + t;          // 27648 groups: 1536 rows x 18
        const float4* s4 = reinterpret_cast<const float4*>(f3);
        float4 a[4], c[4];
        int ci[4], ji[4];
        #pragma unroll
        for (int k = 0; k < 4; k++) {
            int i = i0 + k * 256;
            ci[k] = i / 18; ji[k] = i - ci[k] * 18;
            a[k] = s4[ci[k] * 36 + ji[k] * 2];
            c[k] = s4[ci[k] * 36 + ji[k] * 2 + 1];
        }
        #pragma unroll
        for (int k = 0; k < 4; k++)
            reinterpret_cast<uint4*>(g_F3)[ci[k] * 24 + ji[k]] = pack8(a[k], c[k]);
    } else if (b < 926) {
        int i0 = (b - 917) * 1024 + t;          // 9216 pad groups: 1536 rows x 6
        #pragma unroll
        for (int k = 0; k < 4; k++) {
            int i = i0 + k * 256;
            int c = i / 6, j = i - c * 6;
            reinterpret_cast<uint4*>(g_F3)[c * 24 + 18 + j] = make_uint4(0, 0, 0, 0);
        }
    } else {
        int i0 = (b - 926) * 1024 + t;          // 73728: 512 rows x 144 float4
        #pragma unroll
        for (int k = 0; k < 4; k++) {
            int i = i0 + k * 256;
            int kk = i / 144, c4 = i - kk * 144;
            out4[kk * 720 + c4] = make_float4(0.f, 0.f, 0.f, 0.f);
        }
    }
}

// ---------------- multi-level split-K fp16 GEMM ----------------
#define BM 64
#define BN 96
#define BK 64
#define A_BYTES (BM*BK*2)             // 8192
#define STB (A_BYTES + BN*BK*2)       // 20480 per stage
#define NSTAGE 4
#define SMEM_SZ (NSTAGE*STB + 1024)

__device__ __forceinline__ void cp16(uint32_t d, const void* s) {
    asm volatile("cp.async.cg.shared.global [%0], [%1], 16;\n" :: "r"(d), "l"(s));
}
__device__ __forceinline__ void ldm_x4(uint32_t &r0, uint32_t &r1, uint32_t &r2, uint32_t &r3, uint32_t addr) {
    asm volatile("ldmatrix.sync.aligned.m8n8.x4.shared.b16 {%0,%1,%2,%3}, [%4];\n"
                 : "=r"(r0),"=r"(r1),"=r"(r2),"=r"(r3) : "r"(addr));
}
__device__ __forceinline__ void ldm_x2(uint32_t &r0, uint32_t &r1, uint32_t addr) {
    asm volatile("ldmatrix.sync.aligned.m8n8.x2.shared.b16 {%0,%1}, [%2];\n"
                 : "=r"(r0),"=r"(r1) : "r"(addr));
}
__device__ __forceinline__ void mma16816(float* d, const uint32_t* a, const uint32_t* b) {
    asm volatile("mma.sync.aligned.m16n8k16.row.col.f32.f16.f16.f32 "
                 "{%0,%1,%2,%3}, {%4,%5,%6,%7}, {%8,%9}, {%0,%1,%2,%3};\n"
                 : "+f"(d[0]),"+f"(d[1]),"+f"(d[2]),"+f"(d[3])
                 : "r"(a[0]),"r"(a[1]),"r"(a[2]),"r"(a[3]),"r"(b[0]),"r"(b[1]));
}

__device__ __forceinline__ void load_stage(uint32_t sb, const __half* Ab, const __half* Bb,
                                           int rs, int bm0, int bn0, int kt, int slot, int tid) {
    uint32_t aS = sb + (uint32_t)slot * STB;
    uint32_t bS = aS + A_BYTES;
    int ch = tid & 7, r0 = tid >> 3;
    const __half* ap = Ab + (size_t)bm0 * rs + kt * BK + ch * 8;
    const __half* bp = Bb + (size_t)bn0 * rs + kt * BK + ch * 8;
    #pragma unroll
    for (int r = r0; r < BM; r += 32)
        cp16(aS + (r * 8 + (ch ^ (r & 7))) * 16, ap + (size_t)r * rs);
    #pragma unroll
    for (int r = r0; r < BN; r += 32)
        cp16(bS + (r * 8 + (ch ^ (r & 7))) * 16, bp + (size_t)r * rs);
}

// Flat CTA decode: [0,128) L0 (2n x 8m x 8sp), [128,256) L1 (4n x 8m x 4sp),
//                  [256,320) L2 (8n x 8m), [320,448) L3 (16n x 8m)
__global__ __launch_bounds__(256, 2) void k_gemm(float* __restrict__ out) {
    extern __shared__ __align__(1024) char smem_raw[];
    uint32_t sb = ((uint32_t)__cvta_generic_to_shared(smem_raw) + 1023) & ~1023u;
    const int tid = threadIdx.x, warp = tid >> 5, lane = tid & 31;
    const int wm = (warp >> 2) * 32;      // 2 M-warps
    const int wn = (warp & 3) * 24;       // 4 N-warps, warp tile 32x24

    int bx = blockIdx.x;
    int level, nt, mt, sp;
    if (bx < 128)      { level = 0; sp = bx & 7; int r = bx >> 3; nt = r & 1; mt = r >> 1; }
    else if (bx < 256) { level = 1; int l2 = bx - 128; sp = l2 & 3; int r = l2 >> 2; nt = r & 3; mt = r >> 2; }
    else if (bx < 320) { level = 2; int l2 = bx - 256; sp = 0; nt = l2 & 7;  mt = l2 >> 3; }
    else               { level = 3; int l2 = bx - 320; sp = 0; nt = l2 & 15; mt = l2 >> 4; }

    const __half *Ab, *Bb; int rs, noff, cs, ce;
    if (level == 0) {
        Ab = g_A0; Bb = g_F0; rs = 9216; noff = 0;
        int lo = g_ktlo[mt], nk0 = g_kthi[mt] - lo + 1;
        cs = lo + (nk0 * sp) / 8; ce = lo + (nk0 * (sp + 1)) / 8;
    } else if (level == 1) {
        Ab = g_A1; Bb = g_F1; rs = 2304; noff = 192; cs = 9 * sp; ce = 9 * sp + 9;
    } else if (level == 2) {
        Ab = g_A2; Bb = g_F2; rs = 576;  noff = 576; cs = 0; ce = 9;
    } else {
        Ab = g_A3; Bb = g_F3; rs = 192;  noff = 1344; cs = 0; ce = 3;
    }
    const int nk = ce - cs;
    if (nk <= 0) return;
    const int bm0 = mt * BM, bn0 = nt * BN;

    float acc[2][3][4];
    #pragma unroll
    for (int i = 0; i < 2; i++)
        #pragma unroll
        for (int j = 0; j < 3; j++)
            #pragma unroll
            for (int c = 0; c < 4; c++) acc[i][j][c] = 0.f;

    #pragma unroll
    for (int i = 0; i < 3; i++) {
        if (i < nk) {
            load_stage(sb, Ab, Bb, rs, bm0, bn0, cs + i, i, tid);
            asm volatile("cp.async.commit_group;" ::: "memory");
        }
    }

    for (int j = 0; j < nk; j++) {
        if (j <= nk - 3)      asm volatile("cp.async.wait_group 2;" ::: "memory");
        else if (j == nk - 2) asm volatile("cp.async.wait_group 1;" ::: "memory");
        else                  asm volatile("cp.async.wait_group 0;" ::: "memory");
        __syncthreads();
        if (j + 3 < nk) {
            load_stage(sb, Ab, Bb, rs, bm0, bn0, cs + j + 3, (j + 3) & 3, tid);
            asm volatile("cp.async.commit_group;" ::: "memory");
        }

        const uint32_t aS = sb + (uint32_t)(j & 3) * STB;
        const uint32_t bS = aS + A_BYTES;
        #pragma unroll
        for (int ks = 0; ks < 4; ks++) {
            uint32_t a[2][4];
            #pragma unroll
            for (int mf = 0; mf < 2; mf++) {
                int m  = wm + mf * 16 + (lane & 15);
                int kc = ks * 2 + (lane >> 4);
                ldm_x4(a[mf][0], a[mf][1], a[mf][2], a[mf][3],
                       aS + (m * 8 + (kc ^ (m & 7))) * 16);
            }
            uint32_t b[3][2];
            {
                int g = lane >> 3;
                int n  = wn + (g >> 1) * 8 + (lane & 7);
                int kc = ks * 2 + (g & 1);
                ldm_x4(b[0][0], b[0][1], b[1][0], b[1][1],
                       bS + (n * 8 + (kc ^ (n & 7))) * 16);
            }
            {
                int g = lane >> 3;
                int n  = wn + 16 + (lane & 7);
                int kc = ks * 2 + (g & 1);
                ldm_x2(b[2][0], b[2][1], bS + (n * 8 + (kc ^ (n & 7))) * 16);
            }
            #pragma unroll
            for (int mf = 0; mf < 2; mf++)
                #pragma unroll
                for (int nf = 0; nf < 3; nf++)
                    mma16816(acc[mf][nf], a[mf], b[nf]);
        }
    }

    // Epilogue: scatter rows through perm; split-K levels accumulate atomically.
    int r0 = lane >> 2, c0 = (lane & 3) * 2;
    #pragma unroll
    for (int mf = 0; mf < 2; mf++) {
        int mA = bm0 + wm + mf * 16 + r0;
        int rowA = g_perm[mA];
        int rowB = g_perm[mA + 8];
        #pragma unroll
        for (int nf = 0; nf < 3; nf++) {
            int n = noff + bn0 + wn + nf * 8 + c0;
            float* p0 = &out[(size_t)rowA * CTOT + n];
            float* p1 = &out[(size_t)rowB * CTOT + n];
            if (level <= 1) {
                atomicAdd(p0,     acc[mf][nf][0]);
                atomicAdd(p0 + 1, acc[mf][nf][1]);
                atomicAdd(p1,     acc[mf][nf][2]);
                atomicAdd(p1 + 1, acc[mf][nf][3]);
            } else {
                *(float2*)p0 = make_float2(acc[mf][nf][0], acc[mf][nf][1]);
                *(float2*)p1 = make_float2(acc[mf][nf][2], acc[mf][nf][3]);
            }
        }
    }
}

extern "C" void kernel_launch(void* const* d_in, const int* in_sizes, int n_in,
                              void* d_out, int out_size) {
    const float* feat0 = (const float*)d_in[0];
    const float* feat1 = (const float*)d_in[1];
    const float* feat2 = (const float*)d_in[2];
    const float* feat3 = (const float*)d_in[3];
    const float* boxes = (const float*)d_in[4];
    float* out = (float*)d_out;

    cudaFuncSetAttribute(k_gemm, cudaFuncAttributeMaxDynamicSharedMemorySize, SMEM_SZ);

    k_boxprep<<<1, 256>>>(boxes);
    k_wc<<<998, 256>>>((const float4*)feat0, (const float4*)feat1,
                       (const float4*)feat2, feat3, boxes, (float4*)out);
    k_gemm<<<448, 256, SMEM_SZ>>>(out);
}

// round 12
// speedup vs baseline: 1.1985x; 1.1985x over previous
#include <cuda_runtime.h>
#include <cuda_fp16.h>
#include <cstdint>

#define CTOT 2880
#define NBOX 512

// Raw features in fp16, K-major per level (natural [C][pixel] layout).
__device__ __align__(256) __half g_F0[192 * 9216];
__device__ __align__(256) __half g_F1[384 * 2304];
__device__ __align__(256) __half g_F2[768 * 576];
__device__ __align__(256) __half g_F3[1536 * 192];   // 144 + 48 zero pad
// Projected ROI weight rows per level (sorted box order).
__device__ __align__(256) __half g_A0[NBOX * 9216];
__device__ __align__(256) __half g_A1[NBOX * 2304];
__device__ __align__(256) __half g_A2[NBOX * 576];
__device__ __align__(256) __half g_A3[NBOX * 192];
__device__ int g_perm[NBOX];          // sorted slot -> original box index
__device__ int g_ktlo[8], g_kthi[8];  // per 64-box M-tile: level-0 K-chunk range

// ---------------- boxprep: CLOSED-FORM touched-y range + counting sort + tile K ranges ----
// Sample coords y1 + pp*b + (ss+0.5)*b/gh are monotone in (pp,ss), so the touched range
// is determined by the first (pp=0,ss=0) and last (pp=6,ss=gh-1) samples alone. The
// clamp/i0/i1 logic below is the exact per-sample path applied to those two endpoints.
__global__ __launch_bounds__(256) void k_boxprep(const float* __restrict__ boxes) {
    __shared__ int hist[256], offs[256];
    __shared__ int tlo[8], thi[8];
    __shared__ int wsum[8];
    int t = threadIdx.x;
    hist[t] = 0;
    if (t < 8) { tlo[t] = 1 << 30; thi[t] = -1; }
    __syncthreads();
    int lo[2], hi[2], key[2];
    #pragma unroll
    for (int q = 0; q < 2; q++) {
        int bx = t + q * 256;
        float y1 = boxes[bx * 4 + 1], y2 = boxes[bx * 4 + 3];
        float rh = fmaxf(y2 - y1, 1.f);
        float gh = fminf(fmaxf(ceilf(rh / 7.f), 1.f), 8.f);
        float bb = rh / 7.f;
        float half_step = 0.5f * bb / gh;
        // first sample (pp=0, ss=0)
        float cmin = y1 + half_step;
        int ymin;
        {
            float c = fmaxf(cmin, 0.f);
            int i0 = (int)floorf(c);
            if (i0 > 95) i0 = 95;
            ymin = i0;
        }
        // last sample (pp=6, ss=gh-1): y1 + 6b + (gh-0.5)*b/gh = y1 + rh - half_step
        float cmax = y1 + rh - half_step;
        int ymax;
        {
            float c = fmaxf(cmax, 0.f);
            int i0 = (int)floorf(c);
            int i1 = (i0 >= 95) ? 95 : i0 + 1;
            ymax = i1;
        }
        lo[q] = (ymin * 96) / 64;
        hi[q] = (ymax * 96 + 95) / 64;
        key[q] = ymin + ymax;
        atomicAdd(&hist[key[q]], 1);
    }
    __syncthreads();
    // Parallel exclusive prefix scan over 256 bins (warp shuffles + warp-sum scan).
    {
        int h = hist[t];
        int v = h;
        #pragma unroll
        for (int d = 1; d < 32; d <<= 1) {
            int n = __shfl_up_sync(0xFFFFFFFFu, v, d);
            if ((t & 31) >= d) v += n;
        }
        if ((t & 31) == 31) wsum[t >> 5] = v;
        __syncthreads();
        if (t < 8) {
            int w = wsum[t];
            #pragma unroll
            for (int d = 1; d < 8; d <<= 1) {
                int n = __shfl_up_sync(0xFFu, w, d);
                if (t >= d) w += n;
            }
            wsum[t] = w;
        }
        __syncthreads();
        offs[t] = v - h + ((t >= 32) ? wsum[(t >> 5) - 1] : 0);
    }
    __syncthreads();
    #pragma unroll
    for (int q = 0; q < 2; q++) {
        int pos = atomicAdd(&offs[key[q]], 1);
        g_perm[pos] = t + q * 256;
        atomicMin(&tlo[pos >> 6], lo[q]);
        atomicMax(&thi[pos >> 6], hi[q]);
    }
    __syncthreads();
    if (t < 8) { g_ktlo[t] = tlo[t]; g_kthi[t] = thi[t]; }
}

// ---------------- fused weights + converts + pad + out-stripe zero ----------------
// Block ranges: [0,512) per-box weights, [512,728) cvt0, [728,836) cvt1, [836,890) cvt2,
// [890,917) cvt3 data, [917,926) cvt3 pad, [926,998) zero out[:, 0:576).
__device__ __forceinline__ uint4 pack8(float4 a, float4 b) {
    __half2 h[4];
    h[0] = __floats2half2_rn(a.x, a.y);
    h[1] = __floats2half2_rn(a.z, a.w);
    h[2] = __floats2half2_rn(b.x, b.y);
    h[3] = __floats2half2_rn(b.z, b.w);
    return *reinterpret_cast<uint4*>(h);
}

__global__ __launch_bounds__(256) void k_wc(
    const float4* __restrict__ f0, const float4* __restrict__ f1,
    const float4* __restrict__ f2, const float*  __restrict__ f3,
    const float*  __restrict__ boxes, float4* __restrict__ out4)
{
    int b = blockIdx.x, t = threadIdx.x;
    if (b < 512) {
        // ---- per-box weights: build Ax/Ay, project through upsample, write A0..A3 ----
        __shared__ float Ax[96], Ay[96];
        __shared__ float AxP[84], AyP[84];   // [0,48) L1, [48,72) L2, [72,84) L3
        __shared__ float s_norm;
        int slot = b;
        int k = g_perm[slot];
        if (t < 96) { Ax[t] = 0.f; Ay[t] = 0.f; }
        if (t < 84) { AxP[t] = 0.f; AyP[t] = 0.f; }
        float x1 = boxes[k*4+0], y1 = boxes[k*4+1];
        float x2 = boxes[k*4+2], y2 = boxes[k*4+3];
        float rw = fmaxf(x2 - x1, 1.0f), rh = fmaxf(y2 - y1, 1.0f);
        float gw = fminf(fmaxf(ceilf(rw / 7.0f), 1.0f), 8.0f);
        float gh = fminf(fmaxf(ceilf(rh / 7.0f), 1.0f), 8.0f);
        if (t == 0) s_norm = 1.0f / (gh * gw * 49.0f);
        __syncthreads();
        if (t < 112) {
            int isY = t >= 56;
            int i = isY ? t - 56 : t;
            int pp = i >> 3, ss = i & 7;
            float lo = isY ? y1 : x1;
            float sz = isY ? rh : rw;
            float g  = isY ? gh : gw;
            float* Aarr = isY ? Ay : Ax;
            if ((float)ss < g) {
                float bb = sz / 7.0f;
                float coord = lo + (float)pp * bb + ((float)ss + 0.5f) * (bb / g);
                if (!(coord < -1.0f || coord > 96.0f)) {
                    float c = fmaxf(coord, 0.0f);
                    int i0 = (int)floorf(c);
                    int i1; float f;
                    if (i0 >= 95) { i0 = 95; i1 = 95; f = 0.f; }
                    else          { i1 = i0 + 1; f = c - (float)i0; }
                    atomicAdd(&Aarr[i0], 1.0f - f);
                    atomicAdd(&Aarr[i1], f);
                }
            }
        }
        __syncthreads();
        // Project through the bilinear upsample: A_l = U_l^T A (separable, per axis).
        if (t < 96) {
            float axv = Ax[t], ayv = Ay[t];
            auto proj = [&](float* dst, float v, int HS, float sc) {
                float Xf = ((float)t + 0.5f) * sc - 0.5f;
                float Xc = fminf(fmaxf(Xf, 0.f), (float)(HS - 1));
                int x0 = min((int)Xc, HS - 2);
                float f = Xc - (float)x0;
                atomicAdd(dst + x0, v * (1.f - f));
                atomicAdd(dst + x0 + 1, v * f);
            };
            proj(AxP + 0,  axv, 48, 0.5f);   proj(AyP + 0,  ayv, 48, 0.5f);
            proj(AxP + 48, axv, 24, 0.25f);  proj(AyP + 48, ayv, 24, 0.25f);
            proj(AxP + 72, axv, 12, 0.125f); proj(AyP + 72, ayv, 12, 0.125f);
        }
        __syncthreads();
        float norm = s_norm;
        // A0: only this tile's K-chunk union (all the GEMM ever reads).
        {
            int plo = g_ktlo[slot >> 6] * 64;
            int phi = (g_kthi[slot >> 6] + 1) * 64;
            __half* row = g_A0 + (size_t)slot * 9216;
            for (int e = plo + t * 8; e < phi; e += 256 * 8) {
                int y = e / 96, x = e - y * 96;
                float vy = norm * Ay[y];
                __align__(16) __half h[8];
                #pragma unroll
                for (int i = 0; i < 8; i++) h[i] = __float2half(vy * Ax[x + i]);
                *(uint4*)(row + e) = *reinterpret_cast<uint4*>(h);
            }
        }
        // A1: 48x48
        {
            __half* row = g_A1 + (size_t)slot * 2304;
            for (int e = t * 8; e < 2304; e += 256 * 8) {
                int y = e / 48, x = e - y * 48;
                float vy = norm * AyP[y];
                __align__(16) __half h[8];
                #pragma unroll
                for (int i = 0; i < 8; i++) h[i] = __float2half(vy * AxP[x + i]);
                *(uint4*)(row + e) = *reinterpret_cast<uint4*>(h);
            }
        }
        // A2: 24x24
        {
            __half* row = g_A2 + (size_t)slot * 576;
            if (t * 8 < 576) {
                int e = t * 8;
                int y = e / 24, x = e - y * 24;
                float vy = norm * AyP[48 + y];
                __align__(16) __half h[8];
                #pragma unroll
                for (int i = 0; i < 8; i++) h[i] = __float2half(vy * AxP[48 + x + i]);
                *(uint4*)(row + e) = *reinterpret_cast<uint4*>(h);
            }
        }
        // A3: 12x12 + zero pad to 192
        {
            __half* row = g_A3 + (size_t)slot * 192;
            if (t < 192) {
                float v = 0.f;
                if (t < 144) v = norm * AyP[72 + t / 12] * AxP[72 + t % 12];
                row[t] = __float2half(v);
            }
        }
    } else if (b < 728) {
        int i0 = (b - 512) * 1024 + t;
        uint4* dst = reinterpret_cast<uint4*>(g_F0);
        float4 a[4], c[4];
        #pragma unroll
        for (int k = 0; k < 4; k++) { int i = i0 + k * 256; a[k] = f0[2*i]; c[k] = f0[2*i+1]; }
        #pragma unroll
        for (int k = 0; k < 4; k++) dst[i0 + k * 256] = pack8(a[k], c[k]);
    } else if (b < 836) {
        int i0 = (b - 728) * 1024 + t;
        uint4* dst = reinterpret_cast<uint4*>(g_F1);
        float4 a[4], c[4];
        #pragma unroll
        for (int k = 0; k < 4; k++) { int i = i0 + k * 256; a[k] = f1[2*i]; c[k] = f1[2*i+1]; }
        #pragma unroll
        for (int k = 0; k < 4; k++) dst[i0 + k * 256] = pack8(a[k], c[k]);
    } else if (b < 890) {
        int i0 = (b - 836) * 1024 + t;
        uint4* dst = reinterpret_cast<uint4*>(g_F2);
        float4 a[4], c[4];
        #pragma unroll
        for (int k = 0; k < 4; k++) { int i = i0 + k * 256; a[k] = f2[2*i]; c[k] = f2[2*i+1]; }
        #pragma unroll
        for (int k = 0; k < 4; k++) dst[i0 + k * 256] = pack8(a[k], c[k]);
    } else if (b < 917) {
        int i0 = (b - 890) * 1024 + t;          // 27648 groups: 1536 rows x 18
        const float4* s4 = reinterpret_cast<const float4*>(f3);
        float4 a[4], c[4];
        int ci[4], ji[4];
        #pragma unroll
        for (int k = 0; k < 4; k++) {
            int i = i0 + k * 256;
            ci[k] = i / 18; ji[k] = i - ci[k] * 18;
            a[k] = s4[ci[k] * 36 + ji[k] * 2];
            c[k] = s4[ci[k] * 36 + ji[k] * 2 + 1];
        }
        #pragma unroll
        for (int k = 0; k < 4; k++)
            reinterpret_cast<uint4*>(g_F3)[ci[k] * 24 + ji[k]] = pack8(a[k], c[k]);
    } else if (b < 926) {
        int i0 = (b - 917) * 1024 + t;          // 9216 pad groups: 1536 rows x 6
        #pragma unroll
        for (int k = 0; k < 4; k++) {
            int i = i0 + k * 256;
            int c = i / 6, j = i - c * 6;
            reinterpret_cast<uint4*>(g_F3)[c * 24 + 18 + j] = make_uint4(0, 0, 0, 0);
        }
    } else {
        int i0 = (b - 926) * 1024 + t;          // 73728: 512 rows x 144 float4
        #pragma unroll
        for (int k = 0; k < 4; k++) {
            int i = i0 + k * 256;
            int kk = i / 144, c4 = i - kk * 144;
            out4[kk * 720 + c4] = make_float4(0.f, 0.f, 0.f, 0.f);
        }
    }
}

// ---------------- multi-level split-K fp16 GEMM ----------------
#define BM 64
#define BN 96
#define BK 64
#define A_BYTES (BM*BK*2)             // 8192
#define STB (A_BYTES + BN*BK*2)       // 20480 per stage
#define NSTAGE 4
#define SMEM_SZ (NSTAGE*STB + 1024)

__device__ __forceinline__ void cp16(uint32_t d, const void* s) {
    asm volatile("cp.async.cg.shared.global [%0], [%1], 16;\n" :: "r"(d), "l"(s));
}
__device__ __forceinline__ void ldm_x4(uint32_t &r0, uint32_t &r1, uint32_t &r2, uint32_t &r3, uint32_t addr) {
    asm volatile("ldmatrix.sync.aligned.m8n8.x4.shared.b16 {%0,%1,%2,%3}, [%4];\n"
                 : "=r"(r0),"=r"(r1),"=r"(r2),"=r"(r3) : "r"(addr));
}
__device__ __forceinline__ void ldm_x2(uint32_t &r0, uint32_t &r1, uint32_t addr) {
    asm volatile("ldmatrix.sync.aligned.m8n8.x2.shared.b16 {%0,%1}, [%2];\n"
                 : "=r"(r0),"=r"(r1) : "r"(addr));
}
__device__ __forceinline__ void mma16816(float* d, const uint32_t* a, const uint32_t* b) {
    asm volatile("mma.sync.aligned.m16n8k16.row.col.f32.f16.f16.f32 "
                 "{%0,%1,%2,%3}, {%4,%5,%6,%7}, {%8,%9}, {%0,%1,%2,%3};\n"
                 : "+f"(d[0]),"+f"(d[1]),"+f"(d[2]),"+f"(d[3])
                 : "r"(a[0]),"r"(a[1]),"r"(a[2]),"r"(a[3]),"r"(b[0]),"r"(b[1]));
}

__device__ __forceinline__ void load_stage(uint32_t sb, const __half* Ab, const __half* Bb,
                                           int rs, int bm0, int bn0, int kt, int slot, int tid) {
    uint32_t aS = sb + (uint32_t)slot * STB;
    uint32_t bS = aS + A_BYTES;
    int ch = tid & 7, r0 = tid >> 3;
    const __half* ap = Ab + (size_t)bm0 * rs + kt * BK + ch * 8;
    const __half* bp = Bb + (size_t)bn0 * rs + kt * BK + ch * 8;
    #pragma unroll
    for (int r = r0; r < BM; r += 32)
        cp16(aS + (r * 8 + (ch ^ (r & 7))) * 16, ap + (size_t)r * rs);
    #pragma unroll
    for (int r = r0; r < BN; r += 32)
        cp16(bS + (r * 8 + (ch ^ (r & 7))) * 16, bp + (size_t)r * rs);
}

// Flat CTA decode: [0,128) L0 (2n x 8m x 8sp), [128,256) L1 (4n x 8m x 4sp),
//                  [256,320) L2 (8n x 8m), [320,448) L3 (16n x 8m)
__global__ __launch_bounds__(256, 2) void k_gemm(float* __restrict__ out) {
    extern __shared__ __align__(1024) char smem_raw[];
    uint32_t sb = ((uint32_t)__cvta_generic_to_shared(smem_raw) + 1023) & ~1023u;
    const int tid = threadIdx.x, warp = tid >> 5, lane = tid & 31;
    const int wm = (warp >> 2) * 32;      // 2 M-warps
    const int wn = (warp & 3) * 24;       // 4 N-warps, warp tile 32x24

    int bx = blockIdx.x;
    int level, nt, mt, sp;
    if (bx < 128)      { level = 0; sp = bx & 7; int r = bx >> 3; nt = r & 1; mt = r >> 1; }
    else if (bx < 256) { level = 1; int l2 = bx - 128; sp = l2 & 3; int r = l2 >> 2; nt = r & 3; mt = r >> 2; }
    else if (bx < 320) { level = 2; int l2 = bx - 256; sp = 0; nt = l2 & 7;  mt = l2 >> 3; }
    else               { level = 3; int l2 = bx - 320; sp = 0; nt = l2 & 15; mt = l2 >> 4; }

    const __half *Ab, *Bb; int rs, noff, cs, ce;
    if (level == 0) {
        Ab = g_A0; Bb = g_F0; rs = 9216; noff = 0;
        int lo = g_ktlo[mt], nk0 = g_kthi[mt] - lo + 1;
        cs = lo + (nk0 * sp) / 8; ce = lo + (nk0 * (sp + 1)) / 8;
    } else if (level == 1) {
        Ab = g_A1; Bb = g_F1; rs = 2304; noff = 192; cs = 9 * sp; ce = 9 * sp + 9;
    } else if (level == 2) {
        Ab = g_A2; Bb = g_F2; rs = 576;  noff = 576; cs = 0; ce = 9;
    } else {
        Ab = g_A3; Bb = g_F3; rs = 192;  noff = 1344; cs = 0; ce = 3;
    }
    const int nk = ce - cs;
    if (nk <= 0) return;
    const int bm0 = mt * BM, bn0 = nt * BN;

    float acc[2][3][4];
    #pragma unroll
    for (int i = 0; i < 2; i++)
        #pragma unroll
        for (int j = 0; j < 3; j++)
            #pragma unroll
            for (int c = 0; c < 4; c++) acc[i][j][c] = 0.f;

    #pragma unroll
    for (int i = 0; i < 3; i++) {
        if (i < nk) {
            load_stage(sb, Ab, Bb, rs, bm0, bn0, cs + i, i, tid);
            asm volatile("cp.async.commit_group;" ::: "memory");
        }
    }

    for (int j = 0; j < nk; j++) {
        if (j <= nk - 3)      asm volatile("cp.async.wait_group 2;" ::: "memory");
        else if (j == nk - 2) asm volatile("cp.async.wait_group 1;" ::: "memory");
        else                  asm volatile("cp.async.wait_group 0;" ::: "memory");
        __syncthreads();
        if (j + 3 < nk) {
            load_stage(sb, Ab, Bb, rs, bm0, bn0, cs + j + 3, (j + 3) & 3, tid);
            asm volatile("cp.async.commit_group;" ::: "memory");
        }

        const uint32_t aS = sb + (uint32_t)(j & 3) * STB;
        const uint32_t bS = aS + A_BYTES;
        #pragma unroll
        for (int ks = 0; ks < 4; ks++) {
            uint32_t a[2][4];
            #pragma unroll
            for (int mf = 0; mf < 2; mf++) {
                int m  = wm + mf * 16 + (lane & 15);
                int kc = ks * 2 + (lane >> 4);
                ldm_x4(a[mf][0], a[mf][1], a[mf][2], a[mf][3],
                       aS + (m * 8 + (kc ^ (m & 7))) * 16);
            }
            uint32_t b[3][2];
            {
                int g = lane >> 3;
                int n  = wn + (g >> 1) * 8 + (lane & 7);
                int kc = ks * 2 + (g & 1);
                ldm_x4(b[0][0], b[0][1], b[1][0], b[1][1],
                       bS + (n * 8 + (kc ^ (n & 7))) * 16);
            }
            {
                int g = lane >> 3;
                int n  = wn + 16 + (lane & 7);
                int kc = ks * 2 + (g & 1);
                ldm_x2(b[2][0], b[2][1], bS + (n * 8 + (kc ^ (n & 7))) * 16);
            }
            #pragma unroll
            for (int mf = 0; mf < 2; mf++)
                #pragma unroll
                for (int nf = 0; nf < 3; nf++)
                    mma16816(acc[mf][nf], a[mf], b[nf]);
        }
    }

    // Epilogue: scatter rows through perm; split-K levels accumulate atomically.
    int r0 = lane >> 2, c0 = (lane & 3) * 2;
    #pragma unroll
    for (int mf = 0; mf < 2; mf++) {
        int mA = bm0 + wm + mf * 16 + r0;
        int rowA = g_perm[mA];
        int rowB = g_perm[mA + 8];
        #pragma unroll
        for (int nf = 0; nf < 3; nf++) {
            int n = noff + bn0 + wn + nf * 8 + c0;
            float* p0 = &out[(size_t)rowA * CTOT + n];
            float* p1 = &out[(size_t)rowB * CTOT + n];
            if (level <= 1) {
                atomicAdd(p0,     acc[mf][nf][0]);
                atomicAdd(p0 + 1, acc[mf][nf][1]);
                atomicAdd(p1,     acc[mf][nf][2]);
                atomicAdd(p1 + 1, acc[mf][nf][3]);
            } else {
                *(float2*)p0 = make_float2(acc[mf][nf][0], acc[mf][nf][1]);
                *(float2*)p1 = make_float2(acc[mf][nf][2], acc[mf][nf][3]);
            }
        }
    }
}

extern "C" void kernel_launch(void* const* d_in, const int* in_sizes, int n_in,
                              void* d_out, int out_size) {
    const float* feat0 = (const float*)d_in[0];
    const float* feat1 = (const float*)d_in[1];
    const float* feat2 = (const float*)d_in[2];
    const float* feat3 = (const float*)d_in[3];
    const float* boxes = (const float*)d_in[4];
    float* out = (float*)d_out;

    cudaFuncSetAttribute(k_gemm, cudaFuncAttributeMaxDynamicSharedMemorySize, SMEM_SZ);

    k_boxprep<<<1, 256>>>(boxes);
    k_wc<<<998, 256>>>((const float4*)feat0, (const float4*)feat1,
                       (const float4*)feat2, feat3, boxes, (float4*)out);
    k_gemm<<<448, 256, SMEM_SZ>>>(out);
}